// round 1
// baseline (speedup 1.0000x reference)
#include <cuda_runtime.h>
#include <cstdint>

#define NN   1024
#define XD   128
#define HID  256
#define HP   128   // h-pairs (HID/2)

// ---------------- scratch (device globals; no allocations) ----------------
// Pair-interleaved transposed activations: layout [hp][n] as float2 (h=2hp, h=2hp+1)
__device__ float  g_hxbT[HP * NN * 2];   // hx + b1, transposed, pair-interleaved
__device__ float  g_hyT [HP * NN * 2];   // hy,      transposed, pair-interleaved
__device__ float  g_c[NN];               // c_i = sum_h hy[i,h]*w2[h]
__device__ float  g_d[NN];               // d_j = sum_h (hx[j,h]+b1[h])*w2[h]
__device__ float2 g_part[NN * 16];       // per (i, j-chunk) partial (max, sumexp)
__device__ float  g_diag[NN];            // T1[i,i] (= T0[i])

// ---------------- packed f32x2 helpers ----------------
__device__ __forceinline__ unsigned long long f32x2_add(unsigned long long a,
                                                        unsigned long long b) {
    unsigned long long r;
    asm("add.rn.f32x2 %0, %1, %2;" : "=l"(r) : "l"(a), "l"(b));
    return r;
}
__device__ __forceinline__ unsigned long long f32x2_fma(unsigned long long a,
                                                        unsigned long long b,
                                                        unsigned long long c) {
    unsigned long long r;
    asm("fma.rn.f32x2 %0, %1, %2, %3;" : "=l"(r) : "l"(a), "l"(b), "l"(c));
    return r;
}

__device__ __forceinline__ float softplus_f(float x) {
    // log(1+e^x) = max(x,0) + log1p(e^{-|x|})
    return fmaxf(x, 0.0f) + log1pf(__expf(-fabsf(x)));
}

// ---------------- Kernel 1: h-projections (two small GEMMs) ----------------
// z=0: out = x @ Wx + b1  -> g_hxbT ; z=1: out = y @ Wy -> g_hyT
// Output written transposed & pair-interleaved: idx = ((h>>1)*NN + n)*2 + (h&1)
__global__ __launch_bounds__(256) void gemm_h(const float* __restrict__ X,
                                              const float* __restrict__ Y,
                                              const float* __restrict__ W1,
                                              const float* __restrict__ b1) {
    const int z = blockIdx.z;
    const float* A = (z == 0) ? X : Y;
    const float* W = W1 + z * XD * HID;       // Wx = W1[0:128], Wy = W1[128:256]
    float* outT    = (z == 0) ? g_hxbT : g_hyT;

    __shared__ float s_a[16][68];  // [k][n], padded
    __shared__ float s_w[16][64];  // [k][h]

    const int tid = threadIdx.x;
    const int tx = tid & 15, ty = tid >> 4;   // tx -> n, ty -> h
    const int gn0 = blockIdx.x * 64;
    const int gh0 = blockIdx.y * 64;

    float acc[4][4];  // [hh][nn]
    #pragma unroll
    for (int a = 0; a < 4; a++)
        #pragma unroll
        for (int b = 0; b < 4; b++) acc[a][b] = 0.0f;

    for (int kc = 0; kc < XD; kc += 16) {
        #pragma unroll
        for (int r = 0; r < 4; r++) {
            int idx = tid + r * 256;
            int k_l = idx & 15, n_l = idx >> 4;          // A tile (transpose)
            s_a[k_l][n_l] = A[(gn0 + n_l) * XD + kc + k_l];
            int h_l = idx & 63, k2 = idx >> 6;           // W tile
            s_w[k2][h_l] = W[(kc + k2) * HID + gh0 + h_l];
        }
        __syncthreads();
        #pragma unroll
        for (int k = 0; k < 16; k++) {
            float4 a4 = *(const float4*)&s_a[k][4 * tx];
            float4 w4 = *(const float4*)&s_w[k][4 * ty];
            float av[4] = {a4.x, a4.y, a4.z, a4.w};
            float wv[4] = {w4.x, w4.y, w4.z, w4.w};
            #pragma unroll
            for (int hh = 0; hh < 4; hh++)
                #pragma unroll
                for (int nn = 0; nn < 4; nn++)
                    acc[hh][nn] = fmaf(wv[hh], av[nn], acc[hh][nn]);
        }
        __syncthreads();
    }

    #pragma unroll
    for (int hh = 0; hh < 4; hh++) {
        int h = gh0 + 4 * ty + hh;
        float bb = (z == 0) ? b1[h] : 0.0f;
        #pragma unroll
        for (int nn = 0; nn < 4; nn++) {
            int n = gn0 + 4 * tx + nn;
            outT[((h >> 1) * NN + n) * 2 + (h & 1)] = acc[hh][nn] + bb;
        }
    }
}

// ---------------- Kernel 2: c_i, d_j rank-1 terms ----------------
__global__ __launch_bounds__(256) void cd_kernel(const float* __restrict__ W2) {
    const int i = blockIdx.x * 256 + threadIdx.x;
    const float2* hy = (const float2*)g_hyT;
    const float2* hx = (const float2*)g_hxbT;
    const float2* w2 = (const float2*)W2;
    float c = 0.0f, d = 0.0f;
    #pragma unroll 4
    for (int hp = 0; hp < HP; hp++) {
        float2 w = w2[hp];
        float2 a = hy[hp * NN + i];
        float2 b = hx[hp * NN + i];
        c = fmaf(a.x, w.x, fmaf(a.y, w.y, c));
        d = fmaf(b.x, w.x, fmaf(b.y, w.y, d));
    }
    g_c[i] = c;
    g_d[i] = d;
}

// ---------------- Kernel 3: N^2 pair kernel (packed f32x2 + abs trick) ----
// logit[i,j] = 0.5*(sum_h |hy[i,h]+hxb[j,h]| * w2[h] + c_i + d_j) + b2
// Per block: 64 i x 64 j tile; partial LSE over the block's j-range per i.
__global__ __launch_bounds__(256) void pair_kernel(const float* __restrict__ W2,
                                                   const float* __restrict__ b2) {
    __shared__ unsigned long long s_a[16][64];  // hy  tile [hp][i]
    __shared__ unsigned long long s_b[16][64];  // hxb tile [hp][j]
    __shared__ unsigned long long s_w[HP];      // w2 pairs

    const int tid = threadIdx.x;
    const int tx = tid & 15, ty = tid >> 4;     // tx -> j, ty -> i
    const int i0 = blockIdx.y * 64;
    const int j0 = blockIdx.x * 64;
    const unsigned long long* hyp = (const unsigned long long*)g_hyT;
    const unsigned long long* hxp = (const unsigned long long*)g_hxbT;

    if (tid < HP) s_w[tid] = ((const unsigned long long*)W2)[tid];

    unsigned long long acc[4][4];
    #pragma unroll
    for (int a = 0; a < 4; a++)
        #pragma unroll
        for (int b = 0; b < 4; b++) acc[a][b] = 0ULL;

    for (int hc = 0; hc < HP; hc += 16) {
        __syncthreads();   // also covers s_w on first iteration
        #pragma unroll
        for (int r = 0; r < 4; r++) {
            int idx = tid + r * 256;
            int i_l = idx & 63, hp_l = idx >> 6;
            s_a[hp_l][i_l] = hyp[(hc + hp_l) * NN + i0 + i_l];
            s_b[hp_l][i_l] = hxp[(hc + hp_l) * NN + j0 + i_l];
        }
        __syncthreads();
        #pragma unroll
        for (int hp = 0; hp < 16; hp++) {
            unsigned long long w = s_w[hc + hp];
            ulonglong2 a01 = *(const ulonglong2*)&s_a[hp][4 * ty];
            ulonglong2 a23 = *(const ulonglong2*)&s_a[hp][4 * ty + 2];
            ulonglong2 b01 = *(const ulonglong2*)&s_b[hp][4 * tx];
            ulonglong2 b23 = *(const ulonglong2*)&s_b[hp][4 * tx + 2];
            unsigned long long av[4] = {a01.x, a01.y, a23.x, a23.y};
            unsigned long long bv[4] = {b01.x, b01.y, b23.x, b23.y};
            #pragma unroll
            for (int ii = 0; ii < 4; ii++)
                #pragma unroll
                for (int jj = 0; jj < 4; jj++) {
                    unsigned long long zz = f32x2_add(av[ii], bv[jj]);
                    zz &= 0x7FFFFFFF7FFFFFFFULL;           // |z| both halves (2x LOP3)
                    acc[ii][jj] = f32x2_fma(zz, w, acc[ii][jj]);
                }
        }
    }

    // ---- epilogue: logits -> softplus -> per-i partial LSE over block's j's
    const float b2v = b2[0];
    float cv[4], dv[4];
    #pragma unroll
    for (int ii = 0; ii < 4; ii++) cv[ii] = g_c[i0 + 4 * ty + ii];
    #pragma unroll
    for (int jj = 0; jj < 4; jj++) dv[jj] = g_d[j0 + 4 * tx + jj];

    float t1[4][4];
    #pragma unroll
    for (int ii = 0; ii < 4; ii++) {
        #pragma unroll
        for (int jj = 0; jj < 4; jj++) {
            unsigned long long v = acc[ii][jj];
            float lo = __uint_as_float((unsigned int)v);
            float hi = __uint_as_float((unsigned int)(v >> 32));
            float sabs = lo + hi;
            float logit = 0.5f * (sabs + cv[ii] + dv[jj]) + b2v;
            float t = softplus_f(logit);
            t1[ii][jj] = t;
            int gi = i0 + 4 * ty + ii;
            int gj = j0 + 4 * tx + jj;
            if (gi == gj) g_diag[gi] = t;
        }
    }

    // per-i online (max, sumexp) over this block's 64 j's:
    // thread-local over 4 jj, then butterfly over the 16 tx lanes.
    #pragma unroll
    for (int ii = 0; ii < 4; ii++) {
        float m = fmaxf(fmaxf(t1[ii][0], t1[ii][1]), fmaxf(t1[ii][2], t1[ii][3]));
        float s = __expf(t1[ii][0] - m) + __expf(t1[ii][1] - m) +
                  __expf(t1[ii][2] - m) + __expf(t1[ii][3] - m);
        #pragma unroll
        for (int dlt = 8; dlt >= 1; dlt >>= 1) {
            float mo = __shfl_xor_sync(0xFFFFFFFFu, m, dlt);
            float so = __shfl_xor_sync(0xFFFFFFFFu, s, dlt);
            float mn = fmaxf(m, mo);
            s = s * __expf(m - mn) + so * __expf(mo - mn);
            m = mn;
        }
        if (tx == 0) g_part[(i0 + 4 * ty + ii) * 16 + blockIdx.x] = make_float2(m, s);
    }
}

// ---------------- Kernel 4: merge partials + means -> scalar ----------------
__global__ __launch_bounds__(1024) void final_kernel(float* __restrict__ out) {
    const int i = threadIdx.x;
    float2 p = g_part[i * 16 + 0];
    float m = p.x, s = p.y;
    #pragma unroll
    for (int k = 1; k < 16; k++) {
        float2 q = g_part[i * 16 + k];
        float mn = fmaxf(m, q.x);
        s = s * __expf(m - mn) + q.y * __expf(q.x - mn);
        m = mn;
    }
    float lse = m + __logf(s);
    float t0  = g_diag[i];

    __shared__ float s1[1024];
    __shared__ float s2[1024];
    s1[i] = t0;
    s2[i] = lse;
    __syncthreads();
    #pragma unroll
    for (int st = 512; st > 0; st >>= 1) {
        if (i < st) { s1[i] += s1[i + st]; s2[i] += s2[i + st]; }
        __syncthreads();
    }
    if (i == 0) {
        float invn = 1.0f / (float)NN;
        out[0] = s1[0] * invn - (s2[0] * invn - logf((float)NN));
    }
}

// ---------------- launch ----------------
extern "C" void kernel_launch(void* const* d_in, const int* in_sizes, int n_in,
                              void* d_out, int out_size) {
    (void)in_sizes; (void)n_in; (void)out_size;
    const float* X  = (const float*)d_in[0];  // (1024,128)
    const float* Y  = (const float*)d_in[1];  // (1024,128)
    const float* W1 = (const float*)d_in[2];  // (256,256)
    const float* b1 = (const float*)d_in[3];  // (256,)
    const float* W2 = (const float*)d_in[4];  // (256,1)
    const float* b2 = (const float*)d_in[5];  // (1,)

    gemm_h   <<<dim3(16, 4, 2), 256>>>(X, Y, W1, b1);
    cd_kernel<<<4, 256>>>(W2);
    pair_kernel<<<dim3(16, 16), 256>>>(W2, b2);
    final_kernel<<<1, 1024>>>((float*)d_out);
}

// round 2
// speedup vs baseline: 1.0558x; 1.0558x over previous
#include <cuda_runtime.h>
#include <cstdint>

#define NN   1024
#define XD   128
#define HID  256
#define HP   128   // h-pairs (HID/2)

// ---------------- scratch (device globals; no allocations) ----------------
__device__ float g_hxbT[HP * NN * 2];   // hx + b1, transposed, pair-interleaved [hp][n]{2}
__device__ float g_hyT [HP * NN * 2];   // hy, same layout
__device__ float g_c[NN];               // c_i = sum_h hy[i,h]*w2[h]
__device__ float g_d[NN];               // d_j = sum_h (hx[j,h]+b1[h])*w2[h]
__device__ float g_part[NN * 16];       // per (i, j-block) sum of exp(logit)
__device__ float g_diag[NN];            // T0_i = softplus(logit_ii)
__device__ int   g_ctr;                 // completion counter (reset by last block)

// ---------------- packed f32x2 helpers ----------------
__device__ __forceinline__ unsigned long long f32x2_add(unsigned long long a,
                                                        unsigned long long b) {
    unsigned long long r;
    asm("add.rn.f32x2 %0, %1, %2;" : "=l"(r) : "l"(a), "l"(b));
    return r;
}
__device__ __forceinline__ unsigned long long f32x2_fma(unsigned long long a,
                                                        unsigned long long b,
                                                        unsigned long long c) {
    unsigned long long r;
    asm("fma.rn.f32x2 %0, %1, %2, %3;" : "=l"(r) : "l"(a), "l"(b), "l"(c));
    return r;
}

// ---------------- Kernel 1: h-projections (two small GEMMs) ----------------
// z=0: out = x @ Wx + b1 -> g_hxbT ; z=1: out = y @ Wy -> g_hyT
// Output transposed & pair-interleaved: idx = ((h>>1)*NN + n)*2 + (h&1)
__global__ __launch_bounds__(256) void gemm_h(const float* __restrict__ X,
                                              const float* __restrict__ Y,
                                              const float* __restrict__ W1,
                                              const float* __restrict__ b1) {
    const int z = blockIdx.z;
    const float* A = (z == 0) ? X : Y;
    const float* W = W1 + z * XD * HID;
    float* outT    = (z == 0) ? g_hxbT : g_hyT;

    __shared__ float s_a[16][68];
    __shared__ float s_w[16][64];

    const int tid = threadIdx.x;
    const int tx = tid & 15, ty = tid >> 4;
    const int gn0 = blockIdx.x * 64;
    const int gh0 = blockIdx.y * 64;

    float acc[4][4];
    #pragma unroll
    for (int a = 0; a < 4; a++)
        #pragma unroll
        for (int b = 0; b < 4; b++) acc[a][b] = 0.0f;

    for (int kc = 0; kc < XD; kc += 16) {
        #pragma unroll
        for (int r = 0; r < 4; r++) {
            int idx = tid + r * 256;
            int k_l = idx & 15, n_l = idx >> 4;
            s_a[k_l][n_l] = A[(gn0 + n_l) * XD + kc + k_l];
            int h_l = idx & 63, k2 = idx >> 6;
            s_w[k2][h_l] = W[(kc + k2) * HID + gh0 + h_l];
        }
        __syncthreads();
        #pragma unroll
        for (int k = 0; k < 16; k++) {
            float4 a4 = *(const float4*)&s_a[k][4 * tx];
            float4 w4 = *(const float4*)&s_w[k][4 * ty];
            float av[4] = {a4.x, a4.y, a4.z, a4.w};
            float wv[4] = {w4.x, w4.y, w4.z, w4.w};
            #pragma unroll
            for (int hh = 0; hh < 4; hh++)
                #pragma unroll
                for (int nn = 0; nn < 4; nn++)
                    acc[hh][nn] = fmaf(wv[hh], av[nn], acc[hh][nn]);
        }
        __syncthreads();
    }

    #pragma unroll
    for (int hh = 0; hh < 4; hh++) {
        int h = gh0 + 4 * ty + hh;
        float bb = (z == 0) ? b1[h] : 0.0f;
        #pragma unroll
        for (int nn = 0; nn < 4; nn++) {
            int n = gn0 + 4 * tx + nn;
            outT[((h >> 1) * NN + n) * 2 + (h & 1)] = acc[hh][nn] + bb;
        }
    }
}

// ---------------- Kernel 2: c_i, d_j rank-1 terms ----------------
__global__ __launch_bounds__(256) void cd_kernel(const float* __restrict__ W2) {
    const int i = blockIdx.x * 256 + threadIdx.x;
    const float2* hy = (const float2*)g_hyT;
    const float2* hx = (const float2*)g_hxbT;
    const float2* w2 = (const float2*)W2;
    float c = 0.0f, d = 0.0f;
    #pragma unroll 4
    for (int hp = 0; hp < HP; hp++) {
        float2 w = w2[hp];
        float2 a = hy[hp * NN + i];
        float2 b = hx[hp * NN + i];
        c = fmaf(a.x, w.x, fmaf(a.y, w.y, c));
        d = fmaf(b.x, w.x, fmaf(b.y, w.y, d));
    }
    g_c[i] = c;
    g_d[i] = d;
}

// ---------------- Kernel 3: N^2 pair kernel + fused final reduction -------
// logit[i,j] = 0.5*(sum_h |hy[i,h]+hxb[j,h]|*w2[h] + c_i + d_j) + b2
// exp(softplus(logit)) = 1 + exp(logit)  =>  lse_i = log(1024 + sum_j e^logit)
// Block tile 64i x 64j, 128 threads, per-thread 4i x 8j (conflict-free LDS).
__global__ __launch_bounds__(128) void pair_kernel(const float* __restrict__ W2,
                                                   const float* __restrict__ b2,
                                                   float* __restrict__ out) {
    __shared__ unsigned long long s_a[16][64];   // hy  [hp][i]
    __shared__ unsigned long long s_b[16][64];   // hxb [hp][j]
    __shared__ unsigned long long s_w[HP];
    __shared__ bool  s_last;
    __shared__ float s_red[8];

    const int tid = threadIdx.x;
    const int jt = tid & 7, it = tid >> 3;       // jt: 8 j-threads, it: 16 i-threads
    const int i0 = blockIdx.y * 64;
    const int j0 = blockIdx.x * 64;
    const unsigned long long* hyp = (const unsigned long long*)g_hyT;
    const unsigned long long* hxp = (const unsigned long long*)g_hxbT;

    s_w[tid] = ((const unsigned long long*)W2)[tid];   // 128 threads == HP

    unsigned long long acc[4][8];
    #pragma unroll
    for (int a = 0; a < 4; a++)
        #pragma unroll
        for (int b = 0; b < 8; b++) acc[a][b] = 0ULL;

    for (int hc = 0; hc < HP; hc += 16) {
        __syncthreads();                          // covers s_w on first iter
        #pragma unroll
        for (int r = 0; r < 8; r++) {
            int idx = tid + r * 128;
            int i_l = idx & 63, hp_l = idx >> 6;
            s_a[hp_l][i_l] = hyp[(hc + hp_l) * NN + i0 + i_l];
            s_b[hp_l][i_l] = hxp[(hc + hp_l) * NN + j0 + i_l];
        }
        __syncthreads();
        #pragma unroll
        for (int hp = 0; hp < 16; hp++) {
            unsigned long long w = s_w[hc + hp];
            ulonglong2 A0 = *(const ulonglong2*)&s_a[hp][4 * it];
            ulonglong2 A1 = *(const ulonglong2*)&s_a[hp][4 * it + 2];
            unsigned long long av[4] = {A0.x, A0.y, A1.x, A1.y};
            unsigned long long bv[8];
            #pragma unroll
            for (int q = 0; q < 4; q++) {
                ulonglong2 B = *(const ulonglong2*)&s_b[hp][2 * jt + 16 * q];
                bv[2 * q] = B.x; bv[2 * q + 1] = B.y;
            }
            #pragma unroll
            for (int ii = 0; ii < 4; ii++)
                #pragma unroll
                for (int jx = 0; jx < 8; jx++) {
                    unsigned long long z = f32x2_add(av[ii], bv[jx]) &
                                           0x7FFFFFFF7FFFFFFFULL;
                    acc[ii][jx] = f32x2_fma(z, w, acc[ii][jx]);
                }
        }
    }

    // ---- epilogue: logits -> sum of exp over this block's j's (per i) ----
    const float b2v = b2[0];
    float cv[4], dv[8];
    #pragma unroll
    for (int ii = 0; ii < 4; ii++) cv[ii] = g_c[i0 + 4 * it + ii];
    #pragma unroll
    for (int jx = 0; jx < 8; jx++)
        dv[jx] = g_d[j0 + 2 * jt + (jx & 1) + 16 * (jx >> 1)];

    #pragma unroll
    for (int ii = 0; ii < 4; ii++) {
        const int gi = i0 + 4 * it + ii;
        float s = 0.0f;
        #pragma unroll
        for (int jx = 0; jx < 8; jx++) {
            unsigned long long v = acc[ii][jx];
            float lo = __uint_as_float((unsigned int)v);
            float hi = __uint_as_float((unsigned int)(v >> 32));
            float logit = 0.5f * ((lo + hi) + cv[ii] + dv[jx]) + b2v;
            s += __expf(logit);
            int gj = j0 + 2 * jt + (jx & 1) + 16 * (jx >> 1);
            if (gi == gj)   // diagonal: T0 = softplus(logit)
                g_diag[gi] = fmaxf(logit, 0.0f) + log1pf(__expf(-fabsf(logit)));
        }
        s += __shfl_xor_sync(0xFFFFFFFFu, s, 1);
        s += __shfl_xor_sync(0xFFFFFFFFu, s, 2);
        s += __shfl_xor_sync(0xFFFFFFFFu, s, 4);
        if (jt == 0) g_part[gi * 16 + blockIdx.x] = s;
    }

    // ---- completion counting: last block performs the final reduction ----
    __threadfence();
    __syncthreads();
    if (tid == 0) {
        int old = atomicAdd(&g_ctr, 1);
        s_last = (old == 16 * 16 - 1);
    }
    __syncthreads();
    if (!s_last) return;
    __threadfence();

    float sumT0 = 0.0f, sumL = 0.0f;
    #pragma unroll
    for (int r = 0; r < 8; r++) {
        int i = tid * 8 + r;
        const float4* p = (const float4*)&g_part[i * 16];
        float4 a = p[0], b = p[1], c = p[2], d = p[3];
        float s = ((a.x + a.y) + (a.z + a.w)) + ((b.x + b.y) + (b.z + b.w)) +
                  ((c.x + c.y) + (c.z + c.w)) + ((d.x + d.y) + (d.z + d.w));
        sumL  += __logf(1024.0f + s);
        sumT0 += g_diag[i];
    }
    #pragma unroll
    for (int dlt = 16; dlt >= 1; dlt >>= 1) {
        sumT0 += __shfl_xor_sync(0xFFFFFFFFu, sumT0, dlt);
        sumL  += __shfl_xor_sync(0xFFFFFFFFu, sumL,  dlt);
    }
    if ((tid & 31) == 0) {
        s_red[tid >> 5]     = sumT0;
        s_red[4 + (tid >> 5)] = sumL;
    }
    __syncthreads();
    if (tid == 0) {
        float t0 = (s_red[0] + s_red[1]) + (s_red[2] + s_red[3]);
        float l  = (s_red[4] + s_red[5]) + (s_red[6] + s_red[7]);
        const float invn = 1.0f / 1024.0f;
        out[0] = t0 * invn - (l * invn - logf(1024.0f));
        g_ctr = 0;   // reset for next graph replay
    }
}

// ---------------- launch ----------------
extern "C" void kernel_launch(void* const* d_in, const int* in_sizes, int n_in,
                              void* d_out, int out_size) {
    (void)in_sizes; (void)n_in; (void)out_size;
    const float* X  = (const float*)d_in[0];
    const float* Y  = (const float*)d_in[1];
    const float* W1 = (const float*)d_in[2];
    const float* b1 = (const float*)d_in[3];
    const float* W2 = (const float*)d_in[4];
    const float* b2 = (const float*)d_in[5];

    gemm_h   <<<dim3(16, 4, 2), 256>>>(X, Y, W1, b1);
    cd_kernel<<<4, 256>>>(W2);
    pair_kernel<<<dim3(16, 16), 128>>>(W2, b2, (float*)d_out);
}

// round 4
// speedup vs baseline: 1.0849x; 1.0276x over previous
#include <cuda_runtime.h>
#include <cstdint>

#define NN   1024
#define XD   128
#define HID  256
#define HP   128   // h-pairs

typedef unsigned long long u64;

// ---------------- scratch (device globals; no allocations) ----------------
__device__ float g_hxbT[HP * NN * 2];   // hx + b1, transposed, pair-interleaved [hp][n]{2}
__device__ float g_hyT [HP * NN * 2];   // hy, same layout
__device__ float g_c[NN];               // c_i = sum_h hy[i,h]*w2[h]
__device__ float g_d[NN];               // d_j = sum_h (hx[j,h]+b1[h])*w2[h]
__device__ float g_part[NN * 32];       // per (i, j-block-half) sum of exp(logit)
__device__ float g_diag[NN];            // T0_i = softplus(logit_ii)
__device__ int   g_ctr;

// ---------------- packed f32x2 helpers ----------------
__device__ __forceinline__ u64 f32x2_add(u64 a, u64 b) {
    u64 r; asm("add.rn.f32x2 %0, %1, %2;" : "=l"(r) : "l"(a), "l"(b)); return r;
}
__device__ __forceinline__ u64 f32x2_fma(u64 a, u64 b, u64 c) {
    u64 r; asm("fma.rn.f32x2 %0, %1, %2, %3;" : "=l"(r) : "l"(a), "l"(b), "l"(c)); return r;
}

// ---------------- Kernel 1: h-projections ----------------
// z=0: g_hxbT = x@Wx + b1 ; z=1: g_hyT = y@Wy
// Tile 32n x 64h, 256 threads (2n x 4h per thread), grid (32,4,2) = 256 blocks.
__global__ __launch_bounds__(256) void gemm_h(const float* __restrict__ X,
                                              const float* __restrict__ Y,
                                              const float* __restrict__ W1,
                                              const float* __restrict__ b1) {
    const int z = blockIdx.z;
    const float* A = (z == 0) ? X : Y;
    const float* W = W1 + z * XD * HID;
    float* outT    = (z == 0) ? g_hxbT : g_hyT;

    __shared__ float s_a[16][34];   // [k][n]
    __shared__ float s_w[16][64];   // [k][h]

    const int tid = threadIdx.x;
    const int tx = tid & 15;        // 16 n-threads (2 n each)
    const int ty = tid >> 4;        // 16 h-threads (4 h each)
    const int gn0 = blockIdx.x * 32;
    const int gh0 = blockIdx.y * 64;

    float acc[4][2];
    #pragma unroll
    for (int a = 0; a < 4; a++) { acc[a][0] = 0.0f; acc[a][1] = 0.0f; }

    for (int kc = 0; kc < XD; kc += 16) {
        #pragma unroll
        for (int r = 0; r < 2; r++) {
            int idx = tid + r * 256;
            int k_l = idx & 15, n_l = idx >> 4;   // n_l 0..31
            s_a[k_l][n_l] = A[(gn0 + n_l) * XD + kc + k_l];
        }
        #pragma unroll
        for (int r = 0; r < 4; r++) {
            int idx = tid + r * 256;
            int h_l = idx & 63, k_l = idx >> 6;
            s_w[k_l][h_l] = W[(kc + k_l) * HID + gh0 + h_l];
        }
        __syncthreads();
        #pragma unroll
        for (int k = 0; k < 16; k++) {
            float2 a2 = *(const float2*)&s_a[k][2 * tx];
            float4 w4 = *(const float4*)&s_w[k][4 * ty];
            float wv[4] = {w4.x, w4.y, w4.z, w4.w};
            #pragma unroll
            for (int hh = 0; hh < 4; hh++) {
                acc[hh][0] = fmaf(wv[hh], a2.x, acc[hh][0]);
                acc[hh][1] = fmaf(wv[hh], a2.y, acc[hh][1]);
            }
        }
        __syncthreads();
    }

    #pragma unroll
    for (int hh = 0; hh < 4; hh++) {
        int h = gh0 + 4 * ty + hh;
        float bb = (z == 0) ? b1[h] : 0.0f;
        #pragma unroll
        for (int nn = 0; nn < 2; nn++) {
            int n = gn0 + 2 * tx + nn;
            outT[((h >> 1) * NN + n) * 2 + (h & 1)] = acc[hh][nn] + bb;
        }
    }
}

// ---------------- Kernel 2: c_i, d_j rank-1 terms ----------------
__global__ __launch_bounds__(256) void cd_kernel(const float* __restrict__ W2) {
    const int i = blockIdx.x * 256 + threadIdx.x;
    const float2* hy = (const float2*)g_hyT;
    const float2* hx = (const float2*)g_hxbT;
    const float2* w2 = (const float2*)W2;
    float c = 0.0f, d = 0.0f;
    #pragma unroll 8
    for (int hp = 0; hp < HP; hp++) {
        float2 w = w2[hp];
        float2 a = hy[hp * NN + i];
        float2 b = hx[hp * NN + i];
        c = fmaf(a.x, w.x, fmaf(a.y, w.y, c));
        d = fmaf(b.x, w.x, fmaf(b.y, w.y, d));
    }
    g_c[i] = c;
    g_d[i] = d;
}

// ---------------- Kernel 3: N^2 pair kernel + fused final reduction -------
// logit[i,j] = 0.5*(sum_h |hy[i,h]+hxb[j,h]|*w2[h] + c_i + d_j) + b2
// lse_i = log(1024 + sum_j e^logit)   [since exp(softplus(x)) = 1+e^x]
// Tile 32i x 64j, 128 threads (4 warps: jh = w&1 -> 32 j per lane-set,
// ig = w>>1 -> 16 i per warp). smem transposed [n][hp] pitch 18 (conflict-free
// LDS.128 on the hot path, broadcasts for a/w).
__global__ __launch_bounds__(128) void pair_kernel(const float* __restrict__ W2,
                                                   const float* __restrict__ b2,
                                                   float* __restrict__ out) {
    __shared__ u64 s_a[32][18];   // [i][hp]
    __shared__ u64 s_b[64][18];   // [j][hp]
    __shared__ u64 s_w[HP];
    __shared__ bool  s_last;
    __shared__ float s_red[8];

    const int tid  = threadIdx.x;
    const int lane = tid & 31, w = tid >> 5;
    const int jh = w & 1, ig = w >> 1;
    const int i0 = blockIdx.y * 32;
    const int j0 = blockIdx.x * 64;
    const int jloc = jh * 32 + lane;
    const u64* hyp = (const u64*)g_hyT;
    const u64* hxp = (const u64*)g_hxbT;

    s_w[tid] = ((const u64*)W2)[tid];   // 128 threads == HP

    u64 acc[16];
    #pragma unroll
    for (int a = 0; a < 16; a++) acc[a] = 0ULL;

    for (int hc = 0; hc < HP; hc += 16) {
        __syncthreads();   // covers s_w on first iter
        #pragma unroll
        for (int r = 0; r < 4; r++) {           // s_a: 32i x 16hp = 512
            int idx = tid + r * 128;
            int i_l = idx & 31, hp_l = idx >> 5;
            s_a[i_l][hp_l] = hyp[(hc + hp_l) * NN + i0 + i_l];
        }
        #pragma unroll
        for (int r = 0; r < 8; r++) {           // s_b: 64j x 16hp = 1024
            int idx = tid + r * 128;
            int j_l = idx & 63, hp_l = idx >> 6;
            s_b[j_l][hp_l] = hxp[(hc + hp_l) * NN + j0 + j_l];
        }
        __syncthreads();
        #pragma unroll
        for (int hq = 0; hq < 8; hq++) {        // 2 h-pairs per step
            ulonglong2 bv = *(const ulonglong2*)&s_b[jloc][2 * hq];
            ulonglong2 wv = *(const ulonglong2*)&s_w[hc + 2 * hq];
            #pragma unroll
            for (int ii = 0; ii < 16; ii++) {
                ulonglong2 av = *(const ulonglong2*)&s_a[ig * 16 + ii][2 * hq];
                u64 z0 = f32x2_add(av.x, bv.x) & 0x7FFFFFFF7FFFFFFFULL;
                acc[ii] = f32x2_fma(z0, wv.x, acc[ii]);
                u64 z1 = f32x2_add(av.y, bv.y) & 0x7FFFFFFF7FFFFFFFULL;
                acc[ii] = f32x2_fma(z1, wv.y, acc[ii]);
            }
        }
    }

    // ---- epilogue: per-i sum of exp over this warp's 32 j's ----
    const float b2v = b2[0];
    const int gj = j0 + jloc;
    const float dv = g_d[gj];
    #pragma unroll
    for (int ii = 0; ii < 16; ii++) {
        const int gi = i0 + ig * 16 + ii;
        u64 v = acc[ii];
        float lo = __uint_as_float((unsigned int)v);
        float hi = __uint_as_float((unsigned int)(v >> 32));
        float logit = 0.5f * ((lo + hi) + g_c[gi] + dv) + b2v;
        float e = __expf(logit);
        if (gi == gj)
            g_diag[gi] = fmaxf(logit, 0.0f) + log1pf(__expf(-fabsf(logit)));
        e += __shfl_xor_sync(0xFFFFFFFFu, e, 16);
        e += __shfl_xor_sync(0xFFFFFFFFu, e, 8);
        e += __shfl_xor_sync(0xFFFFFFFFu, e, 4);
        e += __shfl_xor_sync(0xFFFFFFFFu, e, 2);
        e += __shfl_xor_sync(0xFFFFFFFFu, e, 1);
        if (lane == 0) g_part[gi * 32 + blockIdx.x * 2 + jh] = e;
    }

    // ---- last block does the final reduction ----
    __threadfence();
    __syncthreads();
    if (tid == 0) {
        int old = atomicAdd(&g_ctr, 1);
        s_last = (old == 16 * 32 - 1);
    }
    __syncthreads();
    if (!s_last) return;
    __threadfence();

    float sumT0 = 0.0f, sumL = 0.0f;
    #pragma unroll
    for (int r = 0; r < 8; r++) {
        int i = tid * 8 + r;
        const float4* p = (const float4*)&g_part[i * 32];
        float s = 0.0f;
        #pragma unroll
        for (int q = 0; q < 8; q++) {
            float4 f = p[q];
            s += (f.x + f.y) + (f.z + f.w);
        }
        sumL  += __logf(1024.0f + s);
        sumT0 += g_diag[i];
    }
    #pragma unroll
    for (int dlt = 16; dlt >= 1; dlt >>= 1) {
        sumT0 += __shfl_xor_sync(0xFFFFFFFFu, sumT0, dlt);
        sumL  += __shfl_xor_sync(0xFFFFFFFFu, sumL,  dlt);
    }
    if (lane == 0) { s_red[w] = sumT0; s_red[4 + w] = sumL; }
    __syncthreads();
    if (tid == 0) {
        float t0 = (s_red[0] + s_red[1]) + (s_red[2] + s_red[3]);
        float l  = (s_red[4] + s_red[5]) + (s_red[6] + s_red[7]);
        const float invn = 1.0f / 1024.0f;
        out[0] = t0 * invn - (l * invn - logf(1024.0f));
        g_ctr = 0;
    }
}

// ---------------- launch ----------------
extern "C" void kernel_launch(void* const* d_in, const int* in_sizes, int n_in,
                              void* d_out, int out_size) {
    (void)in_sizes; (void)n_in; (void)out_size;
    const float* X  = (const float*)d_in[0];
    const float* Y  = (const float*)d_in[1];
    const float* W1 = (const float*)d_in[2];
    const float* b1 = (const float*)d_in[3];
    const float* W2 = (const float*)d_in[4];
    const float* b2 = (const float*)d_in[5];

    gemm_h   <<<dim3(32, 4, 2), 256>>>(X, Y, W1, b1);
    cd_kernel<<<4, 256>>>(W2);
    pair_kernel<<<dim3(16, 32), 128>>>(W2, b2, (float*)d_out);
}

// round 5
// speedup vs baseline: 1.2636x; 1.1647x over previous
#include <cuda_runtime.h>
#include <cstdint>

#define NN   1024
#define XD   128
#define HID  256
#define HP   128   // h-pairs

typedef unsigned long long u64;

// ---------------- scratch (device globals; no allocations) ----------------
__device__ float g_hxbT[HP * NN * 2];   // hx + b1, transposed, pair-interleaved [hp][n]{2}
__device__ float g_hyT [HP * NN * 2];   // hy, same layout
__device__ float g_c[NN];               // c_i = sum_h hy[i,h]*w2[h]
__device__ float g_d[NN];               // d_j = sum_h (hx[j,h]+b1[h])*w2[h]
__device__ float g_part[NN * 16];       // per (i, j-block) sum of exp(logit)
__device__ float g_diag[NN];            // T0_i = softplus(logit_ii)
__device__ int   g_ctr;

// ---------------- packed f32x2 helpers ----------------
__device__ __forceinline__ u64 f32x2_add(u64 a, u64 b) {
    u64 r; asm("add.rn.f32x2 %0, %1, %2;" : "=l"(r) : "l"(a), "l"(b)); return r;
}
__device__ __forceinline__ u64 f32x2_fma(u64 a, u64 b, u64 c) {
    u64 r; asm("fma.rn.f32x2 %0, %1, %2, %3;" : "=l"(r) : "l"(a), "l"(b), "l"(c)); return r;
}

// ---------------- Kernel 1: h-projections ----------------
// z=0: g_hxbT = x@Wx + b1 ; z=1: g_hyT = y@Wy
// Tile 32n x 32h, 128 threads (2n x 4h per thread), k-chunks of 64.
// Grid (32, 8, 2) = 512 blocks.
__global__ __launch_bounds__(128) void gemm_h(const float* __restrict__ X,
                                              const float* __restrict__ Y,
                                              const float* __restrict__ W1,
                                              const float* __restrict__ b1) {
    const int z = blockIdx.z;
    const float* A = (z == 0) ? X : Y;
    const float* W = W1 + z * XD * HID;
    float* outT    = (z == 0) ? g_hxbT : g_hyT;

    __shared__ float s_a[64][32];   // [k][n]  8 KB
    __shared__ float s_w[64][32];   // [k][h]  8 KB

    const int tid = threadIdx.x;
    const int tx = tid & 15;        // 16 n-threads, 2 n each
    const int ty = tid >> 4;        // 8 h-threads, 4 h each
    const int gn0 = blockIdx.x * 32;
    const int gh0 = blockIdx.y * 32;

    float acc[4][2];
    #pragma unroll
    for (int a = 0; a < 4; a++) { acc[a][0] = 0.0f; acc[a][1] = 0.0f; }

    for (int kc = 0; kc < XD; kc += 64) {
        // fill s_a (transposed): thread handles n = tid&31, k-quad = tid>>5
        {
            int n_l = tid & 31, kq = tid >> 5;          // kq 0..3 -> 16 k each
            const float* src = A + (gn0 + n_l) * XD + kc + kq * 16;
            #pragma unroll
            for (int q = 0; q < 4; q++) {
                float4 v = *(const float4*)(src + 4 * q);
                s_a[kq * 16 + 4 * q + 0][n_l] = v.x;
                s_a[kq * 16 + 4 * q + 1][n_l] = v.y;
                s_a[kq * 16 + 4 * q + 2][n_l] = v.z;
                s_a[kq * 16 + 4 * q + 3][n_l] = v.w;
            }
        }
        // fill s_w: 64k x 32h = 512 float4, 4 per thread
        #pragma unroll
        for (int r = 0; r < 4; r++) {
            int idx = tid + r * 128;
            int k_l = idx >> 3, h4 = idx & 7;
            float4 v = *(const float4*)(W + (kc + k_l) * HID + gh0 + h4 * 4);
            *(float4*)&s_w[k_l][h4 * 4] = v;
        }
        __syncthreads();
        #pragma unroll 8
        for (int k = 0; k < 64; k++) {
            float2 a2 = *(const float2*)&s_a[k][2 * tx];
            float4 w4 = *(const float4*)&s_w[k][4 * ty];
            float wv[4] = {w4.x, w4.y, w4.z, w4.w};
            #pragma unroll
            for (int hh = 0; hh < 4; hh++) {
                acc[hh][0] = fmaf(wv[hh], a2.x, acc[hh][0]);
                acc[hh][1] = fmaf(wv[hh], a2.y, acc[hh][1]);
            }
        }
        __syncthreads();
    }

    #pragma unroll
    for (int hh = 0; hh < 4; hh++) {
        int h = gh0 + 4 * ty + hh;
        float bb = (z == 0) ? b1[h] : 0.0f;
        #pragma unroll
        for (int nn = 0; nn < 2; nn++) {
            int n = gn0 + 2 * tx + nn;
            outT[((h >> 1) * NN + n) * 2 + (h & 1)] = acc[hh][nn] + bb;
        }
    }
}

// ---------------- Kernel 2: c_i, d_j rank-1 terms (h split in 2) ----------
__global__ __launch_bounds__(256) void cd_kernel(const float* __restrict__ W2) {
    __shared__ float sc[256], sd[256];
    const int tid = threadIdx.x;
    const int i = blockIdx.x * 128 + (tid & 127);
    const int half = tid >> 7;                  // 0 or 1: hp range of 64
    const float2* hy = (const float2*)g_hyT;
    const float2* hx = (const float2*)g_hxbT;
    const float2* w2 = (const float2*)W2;
    float c = 0.0f, d = 0.0f;
    const int hp0 = half * 64;
    #pragma unroll 8
    for (int hp = hp0; hp < hp0 + 64; hp++) {
        float2 w = w2[hp];
        float2 a = hy[hp * NN + i];
        float2 b = hx[hp * NN + i];
        c = fmaf(a.x, w.x, fmaf(a.y, w.y, c));
        d = fmaf(b.x, w.x, fmaf(b.y, w.y, d));
    }
    sc[tid] = c; sd[tid] = d;
    __syncthreads();
    if (tid < 128) {
        g_c[i] = sc[tid] + sc[tid + 128];
        g_d[i] = sd[tid] + sd[tid + 128];
    }
}

// ---------------- Kernel 3: N^2 pair kernel + fused final reduction -------
// logit[i,j] = 0.5*(sum_h |hy[i,h]+hxb[j,h]|*w2[h] + c_i + d_j) + b2
// lse_i = log(1024 + sum_j e^logit)   [exp(softplus(x)) = 1+e^x]
// Tile 32i x 64j, 256 threads = 8 warps; warp w covers i-rows w*4..w*4+3,
// each lane 2 j's (lane, lane+32). 8 pairs/lane -> 4096 warps = 27.7/SM.
__global__ __launch_bounds__(256) void pair_kernel(const float* __restrict__ W2,
                                                   const float* __restrict__ b2,
                                                   float* __restrict__ out) {
    __shared__ u64 s_a[32][18];   // [i][hp], pitch 144B (conflict-free)
    __shared__ u64 s_b[64][18];   // [j][hp]
    __shared__ u64 s_w[HP];
    __shared__ bool  s_last;
    __shared__ float s_red[16];

    const int tid  = threadIdx.x;
    const int lane = tid & 31, w = tid >> 5;    // 8 warps
    const int i0 = blockIdx.y * 32;
    const int j0 = blockIdx.x * 64;
    const u64* hyp = (const u64*)g_hyT;
    const u64* hxp = (const u64*)g_hxbT;

    if (tid < HP) s_w[tid] = ((const u64*)W2)[tid];

    u64 acc[4][2];
    #pragma unroll
    for (int a = 0; a < 4; a++) { acc[a][0] = 0ULL; acc[a][1] = 0ULL; }

    for (int hc = 0; hc < HP; hc += 16) {
        __syncthreads();   // covers s_w on first iter
        #pragma unroll
        for (int r = 0; r < 2; r++) {           // s_a: 32i x 16hp = 512 u64
            int idx = tid + r * 256;
            int i_l = idx & 31, hp_l = idx >> 5;
            s_a[i_l][hp_l] = hyp[(hc + hp_l) * NN + i0 + i_l];
        }
        #pragma unroll
        for (int r = 0; r < 4; r++) {           // s_b: 64j x 16hp = 1024 u64
            int idx = tid + r * 256;
            int j_l = idx & 63, hp_l = idx >> 6;
            s_b[j_l][hp_l] = hxp[(hc + hp_l) * NN + j0 + j_l];
        }
        __syncthreads();
        #pragma unroll
        for (int hq = 0; hq < 8; hq++) {        // 2 h-pairs per step
            ulonglong2 wv = *(const ulonglong2*)&s_w[hc + 2 * hq];
            ulonglong2 b0 = *(const ulonglong2*)&s_b[lane][2 * hq];
            ulonglong2 b1 = *(const ulonglong2*)&s_b[lane + 32][2 * hq];
            #pragma unroll
            for (int ii = 0; ii < 4; ii++) {
                ulonglong2 av = *(const ulonglong2*)&s_a[w * 4 + ii][2 * hq];
                u64 z;
                z = f32x2_add(av.x, b0.x) & 0x7FFFFFFF7FFFFFFFULL;
                acc[ii][0] = f32x2_fma(z, wv.x, acc[ii][0]);
                z = f32x2_add(av.y, b0.y) & 0x7FFFFFFF7FFFFFFFULL;
                acc[ii][0] = f32x2_fma(z, wv.y, acc[ii][0]);
                z = f32x2_add(av.x, b1.x) & 0x7FFFFFFF7FFFFFFFULL;
                acc[ii][1] = f32x2_fma(z, wv.x, acc[ii][1]);
                z = f32x2_add(av.y, b1.y) & 0x7FFFFFFF7FFFFFFFULL;
                acc[ii][1] = f32x2_fma(z, wv.y, acc[ii][1]);
            }
        }
    }

    // ---- epilogue: per-i sum of exp over this block's 64 j's ----
    const float b2v = b2[0];
    const int gj0 = j0 + lane, gj1 = j0 + lane + 32;
    const float d0 = g_d[gj0], d1 = g_d[gj1];
    #pragma unroll
    for (int ii = 0; ii < 4; ii++) {
        const int gi = i0 + w * 4 + ii;
        const float ci = g_c[gi];
        u64 v0 = acc[ii][0], v1 = acc[ii][1];
        float sa0 = __uint_as_float((unsigned)v0) + __uint_as_float((unsigned)(v0 >> 32));
        float sa1 = __uint_as_float((unsigned)v1) + __uint_as_float((unsigned)(v1 >> 32));
        float l0 = 0.5f * (sa0 + ci + d0) + b2v;
        float l1 = 0.5f * (sa1 + ci + d1) + b2v;
        float e = __expf(l0) + __expf(l1);
        if (gi == gj0) g_diag[gi] = fmaxf(l0, 0.0f) + log1pf(__expf(-fabsf(l0)));
        if (gi == gj1) g_diag[gi] = fmaxf(l1, 0.0f) + log1pf(__expf(-fabsf(l1)));
        e += __shfl_xor_sync(0xFFFFFFFFu, e, 16);
        e += __shfl_xor_sync(0xFFFFFFFFu, e, 8);
        e += __shfl_xor_sync(0xFFFFFFFFu, e, 4);
        e += __shfl_xor_sync(0xFFFFFFFFu, e, 2);
        e += __shfl_xor_sync(0xFFFFFFFFu, e, 1);
        if (lane == 0) g_part[gi * 16 + blockIdx.x] = e;
    }

    // ---- last block does the final reduction ----
    __threadfence();
    __syncthreads();
    if (tid == 0) {
        int old = atomicAdd(&g_ctr, 1);
        s_last = (old == 16 * 32 - 1);
    }
    __syncthreads();
    if (!s_last) return;
    __threadfence();

    float sumT0 = 0.0f, sumL = 0.0f;
    #pragma unroll
    for (int r = 0; r < 4; r++) {
        int i = tid * 4 + r;
        const float4* p = (const float4*)&g_part[i * 16];
        float4 a = p[0], b = p[1], c = p[2], d = p[3];
        float s = ((a.x + a.y) + (a.z + a.w)) + ((b.x + b.y) + (b.z + b.w)) +
                  ((c.x + c.y) + (c.z + c.w)) + ((d.x + d.y) + (d.z + d.w));
        sumL  += __logf(1024.0f + s);
        sumT0 += g_diag[i];
    }
    #pragma unroll
    for (int dlt = 16; dlt >= 1; dlt >>= 1) {
        sumT0 += __shfl_xor_sync(0xFFFFFFFFu, sumT0, dlt);
        sumL  += __shfl_xor_sync(0xFFFFFFFFu, sumL,  dlt);
    }
    if (lane == 0) { s_red[w] = sumT0; s_red[8 + w] = sumL; }
    __syncthreads();
    if (tid == 0) {
        float t0 = 0.0f, l = 0.0f;
        #pragma unroll
        for (int q = 0; q < 8; q++) { t0 += s_red[q]; l += s_red[8 + q]; }
        const float invn = 1.0f / 1024.0f;
        out[0] = t0 * invn - (l * invn - logf(1024.0f));
        g_ctr = 0;
    }
}

// ---------------- launch ----------------
extern "C" void kernel_launch(void* const* d_in, const int* in_sizes, int n_in,
                              void* d_out, int out_size) {
    (void)in_sizes; (void)n_in; (void)out_size;
    const float* X  = (const float*)d_in[0];
    const float* Y  = (const float*)d_in[1];
    const float* W1 = (const float*)d_in[2];
    const float* b1 = (const float*)d_in[3];
    const float* W2 = (const float*)d_in[4];
    const float* b2 = (const float*)d_in[5];

    gemm_h   <<<dim3(32, 8, 2), 128>>>(X, Y, W1, b1);
    cd_kernel<<<8, 256>>>(W2);
    pair_kernel<<<dim3(16, 32), 256>>>(W2, b2, (float*)d_out);
}